// round 4
// baseline (speedup 1.0000x reference)
#include <cuda_runtime.h>

// Scratch (no device allocation allowed -> __device__ globals)
__device__ float g_part[512 * 2];  // partial maxes [B*8, C]
__device__ float g_M[2 * 64];      // fused weights W1@W2        [C, D2]
__device__ float g_c[64 * 64];     // per-batch fused bias       [B, D2]
__device__ int   g_s1a = 0, g_s1b = 0;   // sync-1 counters (self-resetting)
__device__ int   g_s2a = 0, g_s2b = 0;   // sync-2 counters (self-resetting)

static const int B_ = 64;
static const int N_ = 32768;
static const int GRID = 592;            // 4 blocks/SM * 148 SMs, all resident
static const int P1_BLOCKS = 512;       // 8 chunks per batch
static const int VBLOCKS = B_ * N_ / 64; // 32768 virtual main blocks

// Software grid barrier. Safe because the whole grid is co-resident
// (592 = 4*148 blocks, <=64 regs via launch bounds, 1024 thr/SM).
// Counters reset themselves: the last block through the second counter
// zeroes both, so every graph replay starts from a clean state.
__device__ __forceinline__ void grid_sync(int* ca, int* cb) {
    __syncthreads();
    __threadfence();
    if (threadIdx.x == 0) {
        atomicAdd(ca, 1);
        while (atomicAdd(ca, 0) < GRID) { __nanosleep(64); }
        int t = atomicAdd(cb, 1);
        if (t == GRID - 1) {
            atomicExch(cb, 0);
            atomicExch(ca, 0);
        }
    }
    __syncthreads();
    __threadfence();
}

__global__ void __launch_bounds__(256, 4)
fused_kernel(const float4* __restrict__ x4,
             const float2* __restrict__ x2,
             const float*  __restrict__ W1,
             const float*  __restrict__ b1,
             const float*  __restrict__ G1,
             const float*  __restrict__ W2,
             const float*  __restrict__ b2,
             float4* __restrict__ out) {
    const int tid = threadIdx.x;
    const int blk = blockIdx.x;

    // ---------------- Phase 1: partial per-batch max (blocks 0..511) -------
    if (blk < P1_BLOCKS) {
        const long long base = (long long)blk * 2048;  // float4 index
        const float NEG_INF = __int_as_float(0xff800000);
        float a0 = NEG_INF, a1 = NEG_INF, b0 = NEG_INF, b1v = NEG_INF;
        float4 v[8];
        #pragma unroll
        for (int j = 0; j < 8; j++)
            v[j] = __ldg(&x4[base + j * 256 + tid]);
        #pragma unroll
        for (int j = 0; j < 8; j += 2) {
            a0  = fmaxf(a0,  fmaxf(v[j].x,     v[j].z));
            a1  = fmaxf(a1,  fmaxf(v[j].y,     v[j].w));
            b0  = fmaxf(b0,  fmaxf(v[j + 1].x, v[j + 1].z));
            b1v = fmaxf(b1v, fmaxf(v[j + 1].y, v[j + 1].w));
        }
        float m0 = fmaxf(a0, b0), m1 = fmaxf(a1, b1v);
        #pragma unroll
        for (int o = 16; o > 0; o >>= 1) {
            m0 = fmaxf(m0, __shfl_xor_sync(0xffffffffu, m0, o));
            m1 = fmaxf(m1, __shfl_xor_sync(0xffffffffu, m1, o));
        }
        __shared__ float s0[8], s1[8];
        const int lane = tid & 31;
        const int w    = tid >> 5;
        if (lane == 0) { s0[w] = m0; s1[w] = m1; }
        __syncthreads();
        if (w == 0 && lane < 8) {
            m0 = s0[lane];
            m1 = s1[lane];
            #pragma unroll
            for (int o = 4; o > 0; o >>= 1) {
                m0 = fmaxf(m0, __shfl_xor_sync(0xffu, m0, o));
                m1 = fmaxf(m1, __shfl_xor_sync(0xffu, m1, o));
            }
            if (lane == 0) { g_part[blk * 2 + 0] = m0; g_part[blk * 2 + 1] = m1; }
        }
    }

    grid_sync(&g_s1a, &g_s1b);

    // ---------------- Phase 1.5: prep (blocks 0..64, threads 0..63) --------
    if (blk < 64 && tid < 64) {
        const int d = tid;
        float beta0 = __int_as_float(0xff800000);
        float beta1 = beta0;
        #pragma unroll
        for (int j = 0; j < 8; j++) {
            beta0 = fmaxf(beta0, g_part[(blk * 8 + j) * 2 + 0]);
            beta1 = fmaxf(beta1, g_part[(blk * 8 + j) * 2 + 1]);
        }
        float acc = b2[d];
        #pragma unroll
        for (int k = 0; k < 32; k++) {
            const float wgt = b1[k] - beta0 * G1[k] - beta1 * G1[32 + k];
            acc = fmaf(wgt, W2[k * 64 + d], acc);
        }
        g_c[blk * 64 + d] = acc;
    } else if (blk == 64 && tid < 64) {
        const int d = tid;
        float a0 = 0.f, a1 = 0.f;
        #pragma unroll
        for (int k = 0; k < 32; k++) {
            const float w2kd = W2[k * 64 + d];
            a0 = fmaf(W1[k],      w2kd, a0);
            a1 = fmaf(W1[32 + k], w2kd, a1);
        }
        g_M[d]      = a0;
        g_M[64 + d] = a1;
    }

    grid_sync(&g_s2a, &g_s2b);

    // ---------------- Phase 2: streaming epilogue --------------------------
    // Virtual block v covers 64 points (one batch each since 64 | 32768).
    // Each thread writes 4 float4 with streaming stores. x reads are L2-hot
    // from phase 1. M is constant -> hoisted; c reloaded per v (L2 hit).
    const int d4 = tid & 15;
    const int pl = tid >> 4;
    const float4 m0 = ((const float4*)g_M)[d4];
    const float4 m1 = ((const float4*)g_M)[16 + d4];

    for (int v = blk; v < VBLOCKS; v += GRID) {
        const int b = v >> 9;  // 512 virtual blocks per batch
        const float4 cc = ((const float4*)g_c)[b * 16 + d4];

        const long long p0    = (long long)v * 64 + pl;
        const long long obase = (long long)v * 1024 + tid;

        float2 xv[4];
        #pragma unroll
        for (int j = 0; j < 4; j++)
            xv[j] = __ldg(&x2[p0 + j * 16]);

        #pragma unroll
        for (int j = 0; j < 4; j++) {
            float4 o;
            o.x = fmaf(xv[j].x, m0.x, fmaf(xv[j].y, m1.x, cc.x));
            o.y = fmaf(xv[j].x, m0.y, fmaf(xv[j].y, m1.y, cc.y));
            o.z = fmaf(xv[j].x, m0.z, fmaf(xv[j].y, m1.z, cc.z));
            o.w = fmaf(xv[j].x, m0.w, fmaf(xv[j].y, m1.w, cc.w));
            __stcs(&out[obase + j * 256], o);
        }
    }
}

extern "C" void kernel_launch(void* const* d_in, const int* in_sizes, int n_in,
                              void* d_out, int out_size) {
    const float* pd = (const float*)d_in[0];   // [64, 32768, 2]
    const float* W1 = (const float*)d_in[1];   // [2, 32]
    const float* b1 = (const float*)d_in[2];   // [32]
    const float* G1 = (const float*)d_in[3];   // [2, 32]
    const float* W2 = (const float*)d_in[4];   // [32, 64]
    const float* b2 = (const float*)d_in[5];   // [64]
    float* out = (float*)d_out;                // [64, 32768, 64]

    fused_kernel<<<GRID, 256>>>((const float4*)pd, (const float2*)pd,
                                W1, b1, G1, W2, b2, (float4*)out);
}

// round 5
// speedup vs baseline: 1.0598x; 1.0598x over previous
#include <cuda_runtime.h>

// Scratch (no device allocation allowed -> __device__ globals)
__device__ float g_part[1024 * 2]; // partial maxes [B*16, C]
__device__ float g_M[2 * 64];      // fused weights W1@W2        [C, D2]
__device__ float g_c[64 * 64];     // per-batch fused bias       [B, D2]
__device__ int   g_cnt = 0;        // last-block ticket (self-resetting)

static const int B_ = 64;
static const int N_ = 32768;
static const int P1_GRID = 1024;        // 16 chunks per batch

// -------- Kernel 1: partial per-batch max + last-block prep --------
// 1024 blocks x 256 threads; each block reduces 1024 float4 (16KB).
// The last block to finish (atomic ticket) performs the final 16-way max
// reduce and computes g_c / g_M, then resets the ticket for graph replay.
__global__ void __launch_bounds__(256)
max_prep_kernel(const float4* __restrict__ x,
                const float*  __restrict__ W1,
                const float*  __restrict__ b1,
                const float*  __restrict__ G1,
                const float*  __restrict__ W2,
                const float*  __restrict__ b2) {
    const int tid = threadIdx.x;
    const int blk = blockIdx.x;
    const float NEG_INF = __int_as_float(0xff800000);

    // ---- block partial max over its 16KB chunk ----
    {
        const long long base = (long long)blk * 1024;   // float4 index
        float m0 = NEG_INF, m1 = NEG_INF;
        #pragma unroll
        for (int j = 0; j < 4; j++) {
            float4 v = __ldg(&x[base + j * 256 + tid]);
            m0 = fmaxf(m0, fmaxf(v.x, v.z));
            m1 = fmaxf(m1, fmaxf(v.y, v.w));
        }
        #pragma unroll
        for (int o = 16; o > 0; o >>= 1) {
            m0 = fmaxf(m0, __shfl_xor_sync(0xffffffffu, m0, o));
            m1 = fmaxf(m1, __shfl_xor_sync(0xffffffffu, m1, o));
        }
        __shared__ float s0[8], s1[8];
        const int lane = tid & 31;
        const int w    = tid >> 5;
        if (lane == 0) { s0[w] = m0; s1[w] = m1; }
        __syncthreads();
        if (tid == 0) {
            #pragma unroll
            for (int j = 1; j < 8; j++) {
                s0[0] = fmaxf(s0[0], s0[j]);
                s1[0] = fmaxf(s1[0], s1[j]);
            }
            g_part[blk * 2 + 0] = s0[0];
            g_part[blk * 2 + 1] = s1[0];
        }
    }

    // ---- elect last block ----
    __shared__ int isLast;
    __threadfence();
    if (tid == 0) {
        int t = atomicAdd(&g_cnt, 1);
        isLast = (t == P1_GRID - 1);
    }
    __syncthreads();
    if (!isLast) return;

    // ---- final reduce: beta[b][c] into shared ----
    __shared__ float sbeta[128];
    if (tid < 128) {
        const int bb = tid >> 1;
        const int ch = tid & 1;
        float m = NEG_INF;
        #pragma unroll
        for (int j = 0; j < 16; j++)
            m = fmaxf(m, g_part[(bb * 16 + j) * 2 + ch]);
        sbeta[tid] = m;
    }
    __syncthreads();

    // ---- g_M: threads 0..63, one output column each ----
    if (tid < 64) {
        const int d = tid;
        float a0 = 0.f, a1 = 0.f;
        #pragma unroll
        for (int k = 0; k < 32; k++) {
            const float w2kd = W2[k * 64 + d];
            a0 = fmaf(W1[k],      w2kd, a0);
            a1 = fmaf(W1[32 + k], w2kd, a1);
        }
        g_M[d]      = a0;
        g_M[64 + d] = a1;
    }

    // ---- g_c: 4096 outputs, 16 per thread, batch hoisted per thread ----
    {
        const int bb    = tid >> 2;        // 0..63
        const int dbase = (tid & 3) * 16;  // 0,16,32,48
        const float beta0 = sbeta[bb * 2 + 0];
        const float beta1 = sbeta[bb * 2 + 1];
        float wv[32];
        #pragma unroll
        for (int k = 0; k < 32; k++)
            wv[k] = b1[k] - beta0 * G1[k] - beta1 * G1[32 + k];
        #pragma unroll
        for (int i = 0; i < 16; i++) {
            const int d = dbase + i;
            float acc = b2[d];
            #pragma unroll
            for (int k = 0; k < 32; k++)
                acc = fmaf(wv[k], W2[k * 64 + d], acc);
            g_c[bb * 64 + d] = acc;
        }
    }

    // ---- reset ticket for next graph replay ----
    __syncthreads();
    if (tid == 0) atomicExch(&g_cnt, 0);
}

// -------- Kernel 2: streaming epilogue: out[p, :] = x[p,:]@M + c[b,:] -----
// 32768 blocks x 256 threads (proven 7.2 TB/s config): block = 64 points in
// one batch, thread writes 4 float4 with streaming (evict-first) stores.
__global__ void __launch_bounds__(256) main_kernel(const float2* __restrict__ x,
                                                   float4* __restrict__ out) {
    const int tid = threadIdx.x;
    const int d4  = tid & 15;        // which float4 of the 64-wide row (fixed)
    const int pl  = tid >> 4;        // point within group (0..15)
    const int b   = blockIdx.x >> 9; // 512 blocks per batch

    const float4 m0 = ((const float4*)g_M)[d4];
    const float4 m1 = ((const float4*)g_M)[16 + d4];
    const float4 cc = ((const float4*)g_c)[b * 16 + d4];

    const long long p0    = (long long)blockIdx.x * 64 + pl;
    const long long obase = (long long)blockIdx.x * 1024 + tid;

    float2 xv[4];
    #pragma unroll
    for (int j = 0; j < 4; j++)
        xv[j] = __ldg(&x[p0 + j * 16]);

    #pragma unroll
    for (int j = 0; j < 4; j++) {
        float4 o;
        o.x = fmaf(xv[j].x, m0.x, fmaf(xv[j].y, m1.x, cc.x));
        o.y = fmaf(xv[j].x, m0.y, fmaf(xv[j].y, m1.y, cc.y));
        o.z = fmaf(xv[j].x, m0.z, fmaf(xv[j].y, m1.z, cc.z));
        o.w = fmaf(xv[j].x, m0.w, fmaf(xv[j].y, m1.w, cc.w));
        __stcs(&out[obase + j * 256], o);
    }
}

extern "C" void kernel_launch(void* const* d_in, const int* in_sizes, int n_in,
                              void* d_out, int out_size) {
    const float* pd = (const float*)d_in[0];   // [64, 32768, 2]
    const float* W1 = (const float*)d_in[1];   // [2, 32]
    const float* b1 = (const float*)d_in[2];   // [32]
    const float* G1 = (const float*)d_in[3];   // [2, 32]
    const float* W2 = (const float*)d_in[4];   // [32, 64]
    const float* b2 = (const float*)d_in[5];   // [64]
    float* out = (float*)d_out;                // [64, 32768, 64]

    max_prep_kernel<<<P1_GRID, 256>>>((const float4*)pd, W1, b1, G1, W2, b2);

    const int blocks = B_ * N_ / 64;           // 32768 blocks, 64 points each
    main_kernel<<<blocks, 256>>>((const float2*)pd, (float4*)out);
}

// round 7
// speedup vs baseline: 1.0621x; 1.0022x over previous
#include <cuda_runtime.h>

// Scratch (no device allocation allowed -> __device__ globals)
__device__ float g_part[1024 * 2]; // partial maxes [B*16, C]
__device__ float g_M[2 * 64];      // fused weights W1@W2        [C, D2]
__device__ float g_c[64 * 64];     // per-batch fused bias       [B, D2]
__device__ int   g_cnt = 0;        // last-block ticket (self-resetting)

static const int B_ = 64;
static const int N_ = 32768;
static const int P1_GRID = 1024;        // 16 chunks per batch

// -------- Kernel 1: partial per-batch max + last-block prep --------
// 1024 blocks x 256 threads; each block reduces 1024 float4 (16KB) with 4
// independent float4 loads per thread (fastest measured shape for this
// reduction). The last block to finish (atomic ticket) does the final 16-way
// max reduce and computes g_c / g_M, then resets the ticket for graph replay.
__global__ void __launch_bounds__(256)
max_prep_kernel(const float4* __restrict__ x,
                const float*  __restrict__ W1,
                const float*  __restrict__ b1,
                const float*  __restrict__ G1,
                const float*  __restrict__ W2,
                const float*  __restrict__ b2) {
    const int tid = threadIdx.x;
    const int blk = blockIdx.x;
    const float NEG_INF = __int_as_float(0xff800000);

    // ---- block partial max over its 16KB chunk ----
    {
        const long long base = (long long)blk * 1024;   // float4 index
        float m0 = NEG_INF, m1 = NEG_INF;
        #pragma unroll
        for (int j = 0; j < 4; j++) {
            float4 v = __ldg(&x[base + j * 256 + tid]);
            m0 = fmaxf(m0, fmaxf(v.x, v.z));
            m1 = fmaxf(m1, fmaxf(v.y, v.w));
        }
        #pragma unroll
        for (int o = 16; o > 0; o >>= 1) {
            m0 = fmaxf(m0, __shfl_xor_sync(0xffffffffu, m0, o));
            m1 = fmaxf(m1, __shfl_xor_sync(0xffffffffu, m1, o));
        }
        __shared__ float s0[8], s1[8];
        const int lane = tid & 31;
        const int w    = tid >> 5;
        if (lane == 0) { s0[w] = m0; s1[w] = m1; }
        __syncthreads();
        if (tid == 0) {
            float r0 = s0[0], r1 = s1[0];
            #pragma unroll
            for (int j = 1; j < 8; j++) {
                r0 = fmaxf(r0, s0[j]);
                r1 = fmaxf(r1, s1[j]);
            }
            g_part[blk * 2 + 0] = r0;
            g_part[blk * 2 + 1] = r1;
        }
    }

    // ---- elect last block ----
    __shared__ int isLast;
    __threadfence();
    if (tid == 0) {
        int t = atomicAdd(&g_cnt, 1);
        isLast = (t == P1_GRID - 1);
    }
    __syncthreads();
    if (!isLast) return;

    // ---- final reduce: beta[b][c] into shared ----
    __shared__ float sbeta[128];
    if (tid < 128) {
        const int bb = tid >> 1;
        const int ch = tid & 1;
        float m = NEG_INF;
        #pragma unroll
        for (int j = 0; j < 16; j++)
            m = fmaxf(m, g_part[(bb * 16 + j) * 2 + ch]);
        sbeta[tid] = m;
    }
    __syncthreads();

    // ---- g_M: threads 0..63, one output column each ----
    if (tid < 64) {
        const int d = tid;
        float a0 = 0.f, a1 = 0.f;
        #pragma unroll
        for (int k = 0; k < 32; k++) {
            const float w2kd = W2[k * 64 + d];
            a0 = fmaf(W1[k],      w2kd, a0);
            a1 = fmaf(W1[32 + k], w2kd, a1);
        }
        g_M[d]      = a0;
        g_M[64 + d] = a1;
    }

    // ---- g_c: 4096 outputs, 16 per thread, batch hoisted per thread ----
    {
        const int bb    = tid >> 2;        // 0..63
        const int dbase = (tid & 3) * 16;  // 0,16,32,48
        const float beta0 = sbeta[bb * 2 + 0];
        const float beta1 = sbeta[bb * 2 + 1];
        float wv[32];
        #pragma unroll
        for (int k = 0; k < 32; k++)
            wv[k] = b1[k] - beta0 * G1[k] - beta1 * G1[32 + k];
        #pragma unroll
        for (int i = 0; i < 16; i++) {
            const int d = dbase + i;
            float acc = b2[d];
            #pragma unroll
            for (int k = 0; k < 32; k++)
                acc = fmaf(wv[k], W2[k * 64 + d], acc);
            g_c[bb * 64 + d] = acc;
        }
    }

    // ---- reset ticket for next graph replay ----
    __syncthreads();
    if (tid == 0) atomicExch(&g_cnt, 0);
}

// -------- Kernel 2: streaming epilogue: out[p, :] = x[p,:]@M + c[b,:] -----
// 32768 blocks x 256 threads (proven 7.2 TB/s config): block = 64 points in
// one batch, thread writes 4 float4 with streaming (evict-first) stores.
__global__ void __launch_bounds__(256) main_kernel(const float2* __restrict__ x,
                                                   float4* __restrict__ out) {
    const int tid = threadIdx.x;
    const int d4  = tid & 15;        // which float4 of the 64-wide row (fixed)
    const int pl  = tid >> 4;        // point within group (0..15)
    const int b   = blockIdx.x >> 9; // 512 blocks per batch

    const float4 m0 = ((const float4*)g_M)[d4];
    const float4 m1 = ((const float4*)g_M)[16 + d4];
    const float4 cc = ((const float4*)g_c)[b * 16 + d4];

    const long long p0    = (long long)blockIdx.x * 64 + pl;
    const long long obase = (long long)blockIdx.x * 1024 + tid;

    float2 xv[4];
    #pragma unroll
    for (int j = 0; j < 4; j++)
        xv[j] = __ldg(&x[p0 + j * 16]);

    #pragma unroll
    for (int j = 0; j < 4; j++) {
        float4 o;
        o.x = fmaf(xv[j].x, m0.x, fmaf(xv[j].y, m1.x, cc.x));
        o.y = fmaf(xv[j].x, m0.y, fmaf(xv[j].y, m1.y, cc.y));
        o.z = fmaf(xv[j].x, m0.z, fmaf(xv[j].y, m1.z, cc.z));
        o.w = fmaf(xv[j].x, m0.w, fmaf(xv[j].y, m1.w, cc.w));
        __stcs(&out[obase + j * 256], o);
    }
}

extern "C" void kernel_launch(void* const* d_in, const int* in_sizes, int n_in,
                              void* d_out, int out_size) {
    const float* pd = (const float*)d_in[0];   // [64, 32768, 2]
    const float* W1 = (const float*)d_in[1];   // [2, 32]
    const float* b1 = (const float*)d_in[2];   // [32]
    const float* G1 = (const float*)d_in[3];   // [2, 32]
    const float* W2 = (const float*)d_in[4];   // [32, 64]
    const float* b2 = (const float*)d_in[5];   // [64]
    float* out = (float*)d_out;                // [64, 32768, 64]

    max_prep_kernel<<<P1_GRID, 256>>>((const float4*)pd, W1, b1, G1, W2, b2);

    const int blocks = B_ * N_ / 64;           // 32768 blocks, 64 points each
    main_kernel<<<blocks, 256>>>((const float2*)pd, (float4*)out);
}